// round 16
// baseline (speedup 1.0000x reference)
#include <cuda_runtime.h>
#include <cuda_fp16.h>
#include <cstdint>
#include <math.h>

#define DD 128
#define KK 32
#define NMAX 50000

// Scratch (allocation-free rule: __device__ globals)
__device__ __half  g_xh[NMAX * DD];       // layer-1 GEMM input (fp16)
__device__ __half  g_msg[NMAX * DD];      // messages (fp16)
__device__ __half2 g_wh[2 * 64 * DD];     // W pre-paired: [layer][k2][n]

// ---------------------------------------------------------------------------
__device__ __forceinline__ void cp16(void* dst_smem, const void* src, bool pred) {
    unsigned sdst = (unsigned)__cvta_generic_to_shared(dst_smem);
    int sz = pred ? 16 : 0;
    asm volatile("cp.async.cg.shared.global [%0], [%1], 16, %2;\n"
                 :: "r"(sdst), "l"(src), "r"(sz));
}

// ---------------------------------------------------------------------------
// Prep: pair W rows (k, k+1) into half2, k2-major layout for direct cp.async.
// ---------------------------------------------------------------------------
__global__ void prep_w_kernel(const float* __restrict__ W, __half2* __restrict__ out) {
    int gid = blockIdx.x * blockDim.x + threadIdx.x;   // 0..16383
    int l   = gid >> 13;
    int rem = gid & 8191;
    int k2  = rem >> 7;
    int n   = rem & 127;
    float a = W[l * 16384 + 2 * k2 * 128 + n];
    float b = W[l * 16384 + (2 * k2 + 1) * 128 + n];
    out[gid] = __floats2half2_rn(a, b);
}

// ---------------------------------------------------------------------------
// One-shot fp16 GEMM, 3 blocks/SM (single wave for 391 tiles):
//   W smem: [k2][col] padded 136 uints/row (34.8KB) — conflict-free frag loads
//   A smem: [row][64 uints] XOR-swizzled, no pad (32KB)  — conflict-free
//   __launch_bounds__(256,3) caps regs ~84; bf loaded per-na to cut liveness.
// ---------------------------------------------------------------------------
#define SWU 136
#define GEMM_SMEM ((64 * SWU + 128 * 64) * 4)

template <typename AT, int MPOW>
__global__ __launch_bounds__(256, 3)
void gemm_tc_kernel(const AT* __restrict__ A,
                    const __half2* __restrict__ Wh,   // [64][128] half2
                    const float* __restrict__ mask,
                    __half* __restrict__ C,
                    int N) {
    extern __shared__ unsigned smemu[];
    unsigned* Wsu = smemu;                 // 64*SWU
    unsigned* Asu = smemu + 64 * SWU;      // 128*64

    int tid  = threadIdx.x;
    int lane = tid & 31;
    int warp = tid >> 5;
    int wr   = warp >> 1;
    int wc   = warp & 1;
    int g    = lane >> 2;
    int tg   = lane & 3;

    int block_row = blockIdx.x * 128;

    // ---- stage W: 2048 granules (16B), 8/thread ----
    #pragma unroll
    for (int i = 0; i < 8; i++) {
        int gi  = tid + i * 256;
        int row = gi >> 5;               // 0..63
        int c   = gi & 31;               // 0..31
        cp16(&Wsu[row * SWU + c * 4], Wh + row * 128 + c * 4, true);
    }

    // ---- stage A: 2048 granules, XOR-swizzled ----
    #pragma unroll
    for (int i = 0; i < 8; i++) {
        int gi   = tid + i * 256;
        int row  = gi >> 4;              // 0..127
        int gc   = gi & 15;              // 0..15
        int grow = block_row + row;
        int dstu = row * 64 + ((gc ^ (row & 7)) << 2);
        if (sizeof(AT) == 2) {
            cp16(&Asu[dstu], (const __half*)A + (size_t)grow * 128 + gc * 8, grow < N);
        } else {
            float4 v0 = make_float4(0.f, 0.f, 0.f, 0.f), v1 = v0;
            if (grow < N) {
                const float* Ap = (const float*)A + (size_t)grow * 128 + gc * 8;
                v0 = *(const float4*)(Ap);
                v1 = *(const float4*)(Ap + 4);
            }
            __half2 h0 = __floats2half2_rn(v0.x, v0.y);
            __half2 h1 = __floats2half2_rn(v0.z, v0.w);
            __half2 h2 = __floats2half2_rn(v1.x, v1.y);
            __half2 h3 = __floats2half2_rn(v1.z, v1.w);
            uint4 u = make_uint4(*(unsigned*)&h0, *(unsigned*)&h1,
                                 *(unsigned*)&h2, *(unsigned*)&h3);
            *(uint4*)&Asu[dstu] = u;
        }
    }
    asm volatile("cp.async.commit_group;\n");
    asm volatile("cp.async.wait_group 0;\n");
    __syncthreads();   // the only block-wide barrier

    float acc[2][8][4];
    #pragma unroll
    for (int ma = 0; ma < 2; ma++)
        #pragma unroll
        for (int na = 0; na < 8; na++)
            #pragma unroll
            for (int i = 0; i < 4; i++) acc[ma][na][i] = 0.f;

    #pragma unroll
    for (int ks = 0; ks < 8; ks++) {
        int k2 = ks * 8;
        unsigned af[2][4];
        #pragma unroll
        for (int ma = 0; ma < 2; ma++) {
            int row = wr * 32 + ma * 16 + g;
            int xr  = (row & 7) << 2;
            int rA  = row * 64;
            int rA8 = rA + 8 * 64;       // (row+8)&7 == row&7
            af[ma][0] = Asu[rA  + ((k2 + tg)     ^ xr)];
            af[ma][1] = Asu[rA8 + ((k2 + tg)     ^ xr)];
            af[ma][2] = Asu[rA  + ((k2 + tg + 4) ^ xr)];
            af[ma][3] = Asu[rA8 + ((k2 + tg + 4) ^ xr)];
        }
        #pragma unroll
        for (int na = 0; na < 8; na++) {
            int cc = wc * 64 + na * 8 + g;
            unsigned b0 = Wsu[(k2 + tg)     * SWU + cc];
            unsigned b1 = Wsu[(k2 + tg + 4) * SWU + cc];
            #pragma unroll
            for (int ma = 0; ma < 2; ma++) {
                asm volatile(
                    "mma.sync.aligned.m16n8k16.row.col.f32.f16.f16.f32 "
                    "{%0,%1,%2,%3}, {%4,%5,%6,%7}, {%8,%9}, {%0,%1,%2,%3};\n"
                    : "+f"(acc[ma][na][0]), "+f"(acc[ma][na][1]),
                      "+f"(acc[ma][na][2]), "+f"(acc[ma][na][3])
                    : "r"(af[ma][0]), "r"(af[ma][1]),
                      "r"(af[ma][2]), "r"(af[ma][3]),
                      "r"(b0), "r"(b1));
            }
        }
    }

    // Epilogue: * mask^MPOW, fp16 stores
    #pragma unroll
    for (int ma = 0; ma < 2; ma++) {
        int r0g = block_row + wr * 32 + ma * 16 + g;
        int r1g = r0g + 8;
        float m0 = (r0g < N) ? mask[r0g] : 0.f;
        float m1 = (r1g < N) ? mask[r1g] : 0.f;
        if (MPOW == 2) { m0 *= m0; m1 *= m1; }
        #pragma unroll
        for (int na = 0; na < 8; na++) {
            int col = wc * 64 + na * 8 + 2 * tg;
            if (r0g < N) {
                __half2 h = __floats2half2_rn(acc[ma][na][0] * m0,
                                              acc[ma][na][1] * m0);
                *(__half2*)(C + (size_t)r0g * 128 + col) = h;
            }
            if (r1g < N) {
                __half2 h = __floats2half2_rn(acc[ma][na][2] * m1,
                                              acc[ma][na][3] * m1);
                *(__half2*)(C + (size_t)r1g * 128 + col) = h;
            }
        }
    }
}

// ---------------------------------------------------------------------------
// Gather (R7 form — empirical best): 2 nodes/warp, 16 lanes/node, 8 cols/lane.
// FUSE_LOGMAP=true applies next-layer log-map and writes fp16; else fp32 out.
// ---------------------------------------------------------------------------
template <bool FUSE_LOGMAP>
__global__ __launch_bounds__(256)
void gather_kernel(const int*    __restrict__ adj,
                   const float*  __restrict__ wgt,
                   const float*  __restrict__ mask,
                   const __half* __restrict__ msg,
                   void* __restrict__ xout,
                   int N) {
    __shared__ int2 pairs[8][2][KK];

    int tid   = threadIdx.x;
    int warp  = tid >> 5;
    int lane  = tid & 31;
    int half  = lane >> 4;
    int hl    = lane & 15;
    int node0 = blockIdx.x * 16 + warp * 2;
    int gnode = node0 + half;

    #pragma unroll
    for (int i = 0; i < 2; i++) {
        int idx = lane + i * 32;
        int h   = idx >> 5;
        int k   = idx & 31;
        int gn  = node0 + h;
        if (gn < N) {
            pairs[warp][h][k].x = adj[(size_t)gn * KK + k];
            pairs[warp][h][k].y = __float_as_int(wgt[(size_t)gn * KK + k]);
        }
    }
    __syncwarp();
    if (gnode >= N) return;

    float acc[8];
    #pragma unroll
    for (int i = 0; i < 8; i++) acc[i] = 0.f;

    #pragma unroll
    for (int k = 0; k < KK; k++) {
        int2 p = pairs[warp][half][k];
        float wk = __int_as_float(p.y);
        uint4 raw = *(const uint4*)(msg + (size_t)p.x * DD + hl * 8);
        float2 f0 = __half22float2(*(__half2*)&raw.x);
        float2 f1 = __half22float2(*(__half2*)&raw.y);
        float2 f2 = __half22float2(*(__half2*)&raw.z);
        float2 f3 = __half22float2(*(__half2*)&raw.w);
        acc[0] = fmaf(wk, f0.x, acc[0]);
        acc[1] = fmaf(wk, f0.y, acc[1]);
        acc[2] = fmaf(wk, f1.x, acc[2]);
        acc[3] = fmaf(wk, f1.y, acc[3]);
        acc[4] = fmaf(wk, f2.x, acc[4]);
        acc[5] = fmaf(wk, f2.y, acc[5]);
        acc[6] = fmaf(wk, f3.x, acc[6]);
        acc[7] = fmaf(wk, f3.y, acc[7]);
    }

    float mk = mask[gnode];
    #pragma unroll
    for (int i = 0; i < 8; i++) acc[i] *= mk;

    float s = 0.f;
    #pragma unroll
    for (int i = 0; i < 8; i++) s = fmaf(acc[i], acc[i], s);
    #pragma unroll
    for (int o = 8; o > 0; o >>= 1) s += __shfl_xor_sync(0xffffffffu, s, o);
    float n  = sqrtf(s);
    float nc = fminf(fmaxf(n, 1e-5f), 15.0f);
    float scale = tanhf(nc) / fmaxf(n, 1e-5f) * mk;

    float x[8];
    #pragma unroll
    for (int i = 0; i < 8; i++) x[i] = fmaxf(acc[i] * scale, 0.f) * mk;

    if (FUSE_LOGMAP) {
        float s2 = 0.f;
        #pragma unroll
        for (int i = 0; i < 8; i++) s2 = fmaf(x[i], x[i], s2);
        #pragma unroll
        for (int o = 8; o > 0; o >>= 1) s2 += __shfl_xor_sync(0xffffffffu, s2, o);
        float n2  = sqrtf(s2);
        float nc2 = fminf(fmaxf(n2, 1e-5f), 1.0f - 1e-5f);
        float ls  = atanhf(nc2) / fmaxf(n2, 1e-5f) * mk;
        #pragma unroll
        for (int i = 0; i < 8; i++) x[i] *= ls;

        __half2 h0 = __floats2half2_rn(x[0], x[1]);
        __half2 h1 = __floats2half2_rn(x[2], x[3]);
        __half2 h2 = __floats2half2_rn(x[4], x[5]);
        __half2 h3 = __floats2half2_rn(x[6], x[7]);
        uint4 u = make_uint4(*(unsigned*)&h0, *(unsigned*)&h1,
                             *(unsigned*)&h2, *(unsigned*)&h3);
        *(uint4*)((__half*)xout + (size_t)gnode * DD + hl * 8) = u;
    } else {
        float* dst = (float*)xout + (size_t)gnode * DD + hl * 8;
        *(float4*)(dst)     = make_float4(x[0], x[1], x[2], x[3]);
        *(float4*)(dst + 4) = make_float4(x[4], x[5], x[6], x[7]);
    }
}

// ---------------------------------------------------------------------------
extern "C" void kernel_launch(void* const* d_in, const int* in_sizes, int n_in,
                              void* d_out, int out_size) {
    const float* node_repr = (const float*)d_in[0];
    const int*   adj       = (const int*)  d_in[1];
    const float* weight    = (const float*)d_in[2];
    const float* mask      = (const float*)d_in[3];
    const float* msg_w     = (const float*)d_in[4];

    int N  = in_sizes[0] / DD;
    int NT = (N + 127) / 128;

    __half*  xbuf;
    __half*  mbuf;
    __half2* whbuf;
    cudaGetSymbolAddress((void**)&xbuf, g_xh);
    cudaGetSymbolAddress((void**)&mbuf, g_msg);
    cudaGetSymbolAddress((void**)&whbuf, g_wh);

    static bool attr_done = false;
    if (!attr_done) {
        cudaFuncSetAttribute(gemm_tc_kernel<float, 2>,
                             cudaFuncAttributeMaxDynamicSharedMemorySize, GEMM_SMEM);
        cudaFuncSetAttribute(gemm_tc_kernel<__half, 1>,
                             cudaFuncAttributeMaxDynamicSharedMemorySize, GEMM_SMEM);
        attr_done = true;
    }

    int gatherBlocks = (N + 15) / 16;

    // Pre-pair both layers' W into half2 (k2-major)
    prep_w_kernel<<<64, 256>>>(msg_w, whbuf);

    // ---- Layer 0 ----  ((x*m)@W*m = m^2*(x@W): mask^2 in epilogue)
    gemm_tc_kernel<float, 2><<<NT, 256, GEMM_SMEM>>>(node_repr, whbuf, mask, mbuf, N);
    gather_kernel<true><<<gatherBlocks, 256>>>(adj, weight, mask, mbuf, xbuf, N);

    // ---- Layer 1 ----  (xbuf fp16, tangent-space * mask)
    gemm_tc_kernel<__half, 1><<<NT, 256, GEMM_SMEM>>>(xbuf, whbuf + 64 * DD, mask, mbuf, N);
    gather_kernel<false><<<gatherBlocks, 256>>>(adj, weight, mask, mbuf, d_out, N);
}